// round 14
// baseline (speedup 1.0000x reference)
#include <cuda_runtime.h>
#include <cstdint>
#include <cstddef>

// CrossLevelAttention via tf32 mma.sync flash attention.
// CTA: 128 threads / 4 warps, 64 q rows (16/warp), BN=64 key tiles,
// cp.async double-buffered K/V (raw fp32, tf32 MMA truncates).
// S-phase K B-frags via ldmatrix.x4; S accumulation in FOUR depth-2 chains.
// P kept in registers (C->A layout via quad shuffles).
// PV software-pipelined one slice behind S.

#define NHEAD 16
#define DH 64
#define CDIM (NHEAD * DH)
#define BM 64
#define BN 64
#define KSK 68            // K tile row stride (floats)
#define KSV 72            // V tile row stride (floats)
#define SCALE 0.125f
#define KFLO (BN * KSK)
#define VFLO (BN * KSV)

__device__ __forceinline__ uint32_t f2tf(float f) {
    uint32_t r;
    asm("cvt.rna.tf32.f32 %0, %1;" : "=r"(r) : "f"(f));
    return r;
}

__device__ __forceinline__ void mma_tf32(
    float& c0, float& c1, float& c2, float& c3,
    uint32_t a0, uint32_t a1, uint32_t a2, uint32_t a3,
    uint32_t b0, uint32_t b1)
{
    asm volatile(
        "mma.sync.aligned.m16n8k8.row.col.f32.tf32.tf32.f32 "
        "{%0,%1,%2,%3}, {%4,%5,%6,%7}, {%8,%9}, {%0,%1,%2,%3};"
        : "+f"(c0), "+f"(c1), "+f"(c2), "+f"(c3)
        : "r"(a0), "r"(a1), "r"(a2), "r"(a3), "r"(b0), "r"(b1));
}

__device__ __forceinline__ void ldsm4(
    uint32_t& r0, uint32_t& r1, uint32_t& r2, uint32_t& r3, uint32_t saddr)
{
    asm volatile("ldmatrix.sync.aligned.m8n8.x4.shared.b16 {%0,%1,%2,%3}, [%4];"
                 : "=r"(r0), "=r"(r1), "=r"(r2), "=r"(r3) : "r"(saddr));
}

__device__ __forceinline__ void cpasync16(void* sdst, const void* gsrc) {
    uint32_t s = (uint32_t)__cvta_generic_to_shared(sdst);
    asm volatile("cp.async.cg.shared.global [%0], [%1], 16;" :: "r"(s), "l"(gsrc));
}
#define CP_COMMIT() asm volatile("cp.async.commit_group;" ::: "memory")

__device__ __forceinline__ void prefetch_tile(
    const float* __restrict__ kb, const float* __restrict__ vb,
    int kt, float* sK, float* sV, int tid)
{
    #pragma unroll
    for (int it = 0; it < 8; it++) {
        int idx = it * 128 + tid;   // 1024 float4 slots
        int row = idx >> 4;
        int c4  = idx & 15;
        cpasync16(sK + row * KSK + c4 * 4, kb + (size_t)(kt + row) * CDIM + c4 * 4);
        cpasync16(sV + row * KSV + c4 * 4, vb + (size_t)(kt + row) * CDIM + c4 * 4);
    }
}

// One attention level; accumulates weighted normalized result into tot[32].
template <bool CAUSAL>
__device__ __forceinline__ void attend_level(
    const float* __restrict__ kbase, const float* __restrict__ vbase,
    int n_keys, int q0, int ln, int g, int c, int tid, int r0q,
    const uint32_t (&qf)[8][4], float (&tot)[32], float lw,
    float* sKd, float* sVd,
    uint32_t kOff /* per-lane ldmatrix byte offset within K tile */)
{
    float o[32];
    #pragma unroll
    for (int i = 0; i < 32; i++) o[i] = 0.f;
    float rs0 = 0.f, rs1 = 0.f;
    const int r1q = r0q + 8;
    const int ntile = n_keys / BN;
    const int qs0 = (ln & ~3) + (c >> 1);
    const int qs1 = qs0 + 2;
    const bool odd = (c & 1);

    const uint32_t kShared0 = (uint32_t)__cvta_generic_to_shared(sKd) + kOff;

    prefetch_tile(kbase, vbase, 0, sKd, sVd, tid);
    CP_COMMIT();

    for (int t = 0; t < ntile; t++) {
        if (t + 1 < ntile) {
            prefetch_tile(kbase, vbase, (t + 1) * BN,
                          sKd + ((t + 1) & 1) * KFLO,
                          sVd + ((t + 1) & 1) * VFLO, tid);
            CP_COMMIT();
            asm volatile("cp.async.wait_group 1;" ::: "memory");
        } else {
            asm volatile("cp.async.wait_group 0;" ::: "memory");
        }
        __syncthreads();

        const uint32_t* uV = reinterpret_cast<const uint32_t*>(sVd + (t & 1) * VFLO);
        const uint32_t kSharedT = kShared0 + (uint32_t)((t & 1) * KFLO * 4);
        const int kt = t * BN;
        const bool dom = CAUSAL && (kt + BN > q0);

        uint32_t pa0 = 0, pa1 = 0, pa2 = 0, pa3 = 0;  // P A-frag of slice s-1

        #pragma unroll
        for (int s = 0; s < 8; s++) {
            // ---- K B-frags for slice s via ldmatrix.x4 (batched first) ----
            uint32_t kb[16];
            const uint32_t sa = kSharedT + (uint32_t)(s * 8 * KSK * 4);
            ldsm4(kb[0],  kb[1],  kb[2],  kb[3],  sa);
            ldsm4(kb[4],  kb[5],  kb[6],  kb[7],  sa + 64);
            ldsm4(kb[8],  kb[9],  kb[10], kb[11], sa + 128);
            ldsm4(kb[12], kb[13], kb[14], kb[15], sa + 192);

            // ---- S slice (s): FOUR independent depth-2 chains ----
            float cA0 = 0.f, cA1 = 0.f, cA2 = 0.f, cA3 = 0.f;  // kk 0,1
            float cB0 = 0.f, cB1 = 0.f, cB2 = 0.f, cB3 = 0.f;  // kk 2,3
            float cC0 = 0.f, cC1 = 0.f, cC2 = 0.f, cC3 = 0.f;  // kk 4,5
            float cD0 = 0.f, cD1 = 0.f, cD2 = 0.f, cD3 = 0.f;  // kk 6,7
            mma_tf32(cA0, cA1, cA2, cA3,
                     qf[0][0], qf[0][1], qf[0][2], qf[0][3], kb[0],  kb[1]);
            mma_tf32(cB0, cB1, cB2, cB3,
                     qf[2][0], qf[2][1], qf[2][2], qf[2][3], kb[4],  kb[5]);
            mma_tf32(cC0, cC1, cC2, cC3,
                     qf[4][0], qf[4][1], qf[4][2], qf[4][3], kb[8],  kb[9]);
            mma_tf32(cD0, cD1, cD2, cD3,
                     qf[6][0], qf[6][1], qf[6][2], qf[6][3], kb[12], kb[13]);
            mma_tf32(cA0, cA1, cA2, cA3,
                     qf[1][0], qf[1][1], qf[1][2], qf[1][3], kb[2],  kb[3]);
            mma_tf32(cB0, cB1, cB2, cB3,
                     qf[3][0], qf[3][1], qf[3][2], qf[3][3], kb[6],  kb[7]);
            mma_tf32(cC0, cC1, cC2, cC3,
                     qf[5][0], qf[5][1], qf[5][2], qf[5][3], kb[10], kb[11]);
            mma_tf32(cD0, cD1, cD2, cD3,
                     qf[7][0], qf[7][1], qf[7][2], qf[7][3], kb[14], kb[15]);

            // ---- PV for slice s-1 (independent: overlaps S(s) chains) ----
            if (s > 0) {
                const int sp = s - 1;
                #pragma unroll
                for (int dt = 0; dt < 8; dt++) {
                    uint32_t b0 = uV[(sp * 8 + c) * KSV + dt * 8 + g];
                    uint32_t b1 = uV[(sp * 8 + c + 4) * KSV + dt * 8 + g];
                    mma_tf32(o[dt * 4 + 0], o[dt * 4 + 1],
                             o[dt * 4 + 2], o[dt * 4 + 3],
                             pa0, pa1, pa2, pa3, b0, b1);
                }
            }

            // ---- consume S(s): 2-level sum tree, exp + causal mask ----
            float s0 = (cA0 + cB0) + (cC0 + cD0);
            float s1 = (cA1 + cB1) + (cC1 + cD1);
            float s2 = (cA2 + cB2) + (cC2 + cD2);
            float s3 = (cA3 + cB3) + (cC3 + cD3);
            float p0, p1, p2, p3;
            if (dom) {
                int k0 = kt + s * 8 + 2 * c;
                p0 = (k0     > r0q) ? 0.f : __expf(s0);
                p1 = (k0 + 1 > r0q) ? 0.f : __expf(s1);
                p2 = (k0     > r1q) ? 0.f : __expf(s2);
                p3 = (k0 + 1 > r1q) ? 0.f : __expf(s3);
            } else {
                p0 = __expf(s0); p1 = __expf(s1);
                p2 = __expf(s2); p3 = __expf(s3);
            }
            // RNA-round p to tf32 so rs and MMA see identical values.
            uint32_t u0 = f2tf(p0), u1 = f2tf(p1);
            uint32_t u2 = f2tf(p2), u3 = f2tf(p3);
            rs0 += __uint_as_float(u0) + __uint_as_float(u1);
            rs1 += __uint_as_float(u2) + __uint_as_float(u3);

            // ---- C-layout -> A-layout via quad shuffles -> pa (for s+1) ----
            uint32_t x00 = __shfl_sync(0xffffffffu, u0, qs0);
            uint32_t x10 = __shfl_sync(0xffffffffu, u1, qs0);
            uint32_t x01 = __shfl_sync(0xffffffffu, u0, qs1);
            uint32_t x11 = __shfl_sync(0xffffffffu, u1, qs1);
            uint32_t x20 = __shfl_sync(0xffffffffu, u2, qs0);
            uint32_t x30 = __shfl_sync(0xffffffffu, u3, qs0);
            uint32_t x21 = __shfl_sync(0xffffffffu, u2, qs1);
            uint32_t x31 = __shfl_sync(0xffffffffu, u3, qs1);
            pa0 = odd ? x10 : x00;
            pa2 = odd ? x11 : x01;
            pa1 = odd ? x30 : x20;
            pa3 = odd ? x31 : x21;
        }

        // ---- drain: PV for slice 7 of this tile ----
        {
            #pragma unroll
            for (int dt = 0; dt < 8; dt++) {
                uint32_t b0 = uV[(7 * 8 + c) * KSV + dt * 8 + g];
                uint32_t b1 = uV[(7 * 8 + c + 4) * KSV + dt * 8 + g];
                mma_tf32(o[dt * 4 + 0], o[dt * 4 + 1],
                         o[dt * 4 + 2], o[dt * 4 + 3],
                         pa0, pa1, pa2, pa3, b0, b1);
            }
        }
        __syncthreads();
    }

    // Reduce row sums across the quad.
    rs0 += __shfl_xor_sync(0xffffffffu, rs0, 1);
    rs0 += __shfl_xor_sync(0xffffffffu, rs0, 2);
    rs1 += __shfl_xor_sync(0xffffffffu, rs1, 1);
    rs1 += __shfl_xor_sync(0xffffffffu, rs1, 2);
    float inv0 = lw / rs0;
    float inv1 = lw / rs1;
    #pragma unroll
    for (int dt = 0; dt < 8; dt++) {
        tot[dt * 4 + 0] = fmaf(o[dt * 4 + 0], inv0, tot[dt * 4 + 0]);
        tot[dt * 4 + 1] = fmaf(o[dt * 4 + 1], inv0, tot[dt * 4 + 1]);
        tot[dt * 4 + 2] = fmaf(o[dt * 4 + 2], inv1, tot[dt * 4 + 2]);
        tot[dt * 4 + 3] = fmaf(o[dt * 4 + 3], inv1, tot[dt * 4 + 3]);
    }
}

__global__ __launch_bounds__(128, 3)
void xlvl_attn_mma_kernel(
    const float* __restrict__ Q,
    const float* __restrict__ K0, const float* __restrict__ V0,
    const float* __restrict__ K1, const float* __restrict__ V1,
    const float* __restrict__ K2, const float* __restrict__ V2,
    const float* __restrict__ logits,
    float* __restrict__ out,
    int T, int T1, int T2)
{
    extern __shared__ __align__(16) float dynsmem[];
    float* sKd = dynsmem;                 // 2 x 64 x 68
    float* sVd = dynsmem + 2 * KFLO;      // 2 x 64 x 72

    const int qb  = (int)(gridDim.x - 1 - blockIdx.x);  // heavy blocks first
    const int h   = blockIdx.y;
    const int b   = blockIdx.z;
    const int tid = threadIdx.x;
    const int w   = tid >> 5;
    const int ln  = tid & 31;
    const int g   = ln >> 2;
    const int c   = ln & 3;
    const int q0  = qb * BM;
    const int r0q = q0 + w * 16 + g;

    // Per-lane ldmatrix byte offset inside a K tile:
    // matrix m = ln>>3 on rows (ln&7), col offset (m>>1)*8 + (m&1)*4 floats.
    const int lm_m = ln >> 3;
    const int lm_r = ln & 7;
    const uint32_t kOff =
        (uint32_t)((lm_r * KSK + (lm_m >> 1) * 8 + (lm_m & 1) * 4) * 4);

    float l0 = logits[0], l1 = logits[1], l2 = logits[2];
    float mx = fmaxf(l0, fmaxf(l1, l2));
    float e0 = __expf(l0 - mx), e1 = __expf(l1 - mx), e2 = __expf(l2 - mx);
    float winv = 1.0f / (e0 + e1 + e2);
    float w0 = e0 * winv, w1 = e1 * winv, w2 = e2 * winv;

    // Q A-fragments (RNA tf32), SCALE folded; shared by all levels.
    uint32_t qf[8][4];
    {
        const float* qp  = Q + ((size_t)(b * NHEAD + h) * T + r0q) * DH;
        const float* qp8 = qp + 8 * DH;
        #pragma unroll
        for (int kk = 0; kk < 8; kk++) {
            qf[kk][0] = f2tf(qp [kk * 8 + c]     * SCALE);
            qf[kk][1] = f2tf(qp8[kk * 8 + c]     * SCALE);
            qf[kk][2] = f2tf(qp [kk * 8 + c + 4] * SCALE);
            qf[kk][3] = f2tf(qp8[kk * 8 + c + 4] * SCALE);
        }
    }

    float tot[32];
    #pragma unroll
    for (int i = 0; i < 32; i++) tot[i] = 0.f;

    attend_level<true>(K0 + (size_t)b * T  * CDIM + h * DH,
                       V0 + (size_t)b * T  * CDIM + h * DH,
                       q0 + BM, q0, ln, g, c, tid, r0q, qf, tot, w0,
                       sKd, sVd, kOff);
    attend_level<false>(K1 + (size_t)b * T1 * CDIM + h * DH,
                        V1 + (size_t)b * T1 * CDIM + h * DH,
                        T1, q0, ln, g, c, tid, r0q, qf, tot, w1,
                        sKd, sVd, kOff);
    attend_level<false>(K2 + (size_t)b * T2 * CDIM + h * DH,
                        V2 + (size_t)b * T2 * CDIM + h * DH,
                        T2, q0, ln, g, c, tid, r0q, qf, tot, w2,
                        sKd, sVd, kOff);

    float* op0 = out + ((size_t)b * T + r0q) * CDIM + h * DH;
    float* op1 = op0 + 8 * CDIM;
    #pragma unroll
    for (int dt = 0; dt < 8; dt++) {
        *reinterpret_cast<float2*>(op0 + dt * 8 + 2 * c) =
            make_float2(tot[dt * 4 + 0], tot[dt * 4 + 1]);
        *reinterpret_cast<float2*>(op1 + dt * 8 + 2 * c) =
            make_float2(tot[dt * 4 + 2], tot[dt * 4 + 3]);
    }
}

extern "C" void kernel_launch(void* const* d_in, const int* in_sizes, int n_in,
                              void* d_out, int out_size)
{
    const float* Q      = (const float*)d_in[0];
    const float* K0     = (const float*)d_in[1];
    const float* V0     = (const float*)d_in[2];
    const float* K1     = (const float*)d_in[3];
    const float* V1     = (const float*)d_in[4];
    const float* K2     = (const float*)d_in[5];
    const float* V2     = (const float*)d_in[6];
    const float* logits = (const float*)d_in[7];
    float* out          = (float*)d_out;

    const int B  = 2;
    const int T  = in_sizes[1] / (B * CDIM);
    const int T1 = in_sizes[3] / (B * CDIM);
    const int T2 = in_sizes[5] / (B * CDIM);

    const int smem = (2 * KFLO + 2 * VFLO) * (int)sizeof(float);  // 71,680 B
    static bool configured = false;
    if (!configured) {
        cudaFuncSetAttribute(xlvl_attn_mma_kernel,
                             cudaFuncAttributeMaxDynamicSharedMemorySize, smem);
        configured = true;
    }

    dim3 grid(T / BM, NHEAD, B);
    xlvl_attn_mma_kernel<<<grid, 128, smem>>>(Q, K0, V0, K1, V1, K2, V2, logits,
                                              out, T, T1, T2);
}

// round 15
// speedup vs baseline: 1.1344x; 1.1344x over previous
#include <cuda_runtime.h>
#include <cstdint>
#include <cstddef>

// CrossLevelAttention via tf32 mma.sync flash attention.
// CTA: 128 threads / 4 warps, 64 q rows (16/warp), BN=64 key tiles,
// cp.async double-buffered K/V (raw fp32, tf32 MMA truncates).
// S-phase K B-frags via ldmatrix.x4 (2 split accumulator chains).
// V rows are PERMUTED within 8-key groups at store time (sigma(n) =
// (n&1)*4 + (n>>1)) so the S C-layout registers are directly the PV
// A-fragment — no shuffles. PV software-pipelined one slice behind S.
// exp via ex2.approx with log2e folded into the Q scale.

#define NHEAD 16
#define DH 64
#define CDIM (NHEAD * DH)
#define BM 64
#define BN 64
#define KSK 68            // K tile row stride (floats)
#define KSV 72            // V tile row stride (floats)
#define SCALE_L2E 0.18033688011112042592f   // 0.125 * log2(e)
#define KFLO (BN * KSK)
#define VFLO (BN * KSV)

__device__ __forceinline__ uint32_t f2tf(float f) {
    uint32_t r;
    asm("cvt.rna.tf32.f32 %0, %1;" : "=r"(r) : "f"(f));
    return r;
}

__device__ __forceinline__ float ex2f(float x) {
    float y;
    asm("ex2.approx.f32 %0, %1;" : "=f"(y) : "f"(x));
    return y;
}

__device__ __forceinline__ void mma_tf32(
    float& c0, float& c1, float& c2, float& c3,
    uint32_t a0, uint32_t a1, uint32_t a2, uint32_t a3,
    uint32_t b0, uint32_t b1)
{
    asm volatile(
        "mma.sync.aligned.m16n8k8.row.col.f32.tf32.tf32.f32 "
        "{%0,%1,%2,%3}, {%4,%5,%6,%7}, {%8,%9}, {%0,%1,%2,%3};"
        : "+f"(c0), "+f"(c1), "+f"(c2), "+f"(c3)
        : "r"(a0), "r"(a1), "r"(a2), "r"(a3), "r"(b0), "r"(b1));
}

__device__ __forceinline__ void ldsm4(
    uint32_t& r0, uint32_t& r1, uint32_t& r2, uint32_t& r3, uint32_t saddr)
{
    asm volatile("ldmatrix.sync.aligned.m8n8.x4.shared.b16 {%0,%1,%2,%3}, [%4];"
                 : "=r"(r0), "=r"(r1), "=r"(r2), "=r"(r3) : "r"(saddr));
}

__device__ __forceinline__ void cpasync16(void* sdst, const void* gsrc) {
    uint32_t s = (uint32_t)__cvta_generic_to_shared(sdst);
    asm volatile("cp.async.cg.shared.global [%0], [%1], 16;" :: "r"(s), "l"(gsrc));
}
#define CP_COMMIT() asm volatile("cp.async.commit_group;" ::: "memory")

__device__ __forceinline__ void prefetch_tile(
    const float* __restrict__ kb, const float* __restrict__ vb,
    int kt, float* sK, float* sV, int tid)
{
    #pragma unroll
    for (int it = 0; it < 8; it++) {
        int idx = it * 128 + tid;   // 1024 float4 slots
        int row = idx >> 4;
        int c4  = idx & 15;
        cpasync16(sK + row * KSK + c4 * 4, kb + (size_t)(kt + row) * CDIM + c4 * 4);
        // V: permute rows within each 8-key group: sigma(n) = (n&1)*4 + (n>>1)
        int vrow = (row & ~7) | (((row & 1) << 2) | ((row & 7) >> 1));
        cpasync16(sV + vrow * KSV + c4 * 4, vb + (size_t)(kt + row) * CDIM + c4 * 4);
    }
}

// One attention level; accumulates weighted normalized result into tot[32].
template <bool CAUSAL>
__device__ __forceinline__ void attend_level(
    const float* __restrict__ kbase, const float* __restrict__ vbase,
    int n_keys, int q0, int ln, int g, int c, int tid, int r0q,
    const uint32_t (&qf)[8][4], float (&tot)[32], float lw,
    float* sKd, float* sVd,
    uint32_t kOff /* per-lane ldmatrix byte offset within K tile */)
{
    float o[32];
    #pragma unroll
    for (int i = 0; i < 32; i++) o[i] = 0.f;
    float rs0 = 0.f, rs1 = 0.f;
    const int r1q = r0q + 8;
    const int ntile = n_keys / BN;

    const uint32_t kShared0 = (uint32_t)__cvta_generic_to_shared(sKd) + kOff;

    prefetch_tile(kbase, vbase, 0, sKd, sVd, tid);
    CP_COMMIT();

    for (int t = 0; t < ntile; t++) {
        if (t + 1 < ntile) {
            prefetch_tile(kbase, vbase, (t + 1) * BN,
                          sKd + ((t + 1) & 1) * KFLO,
                          sVd + ((t + 1) & 1) * VFLO, tid);
            CP_COMMIT();
            asm volatile("cp.async.wait_group 1;" ::: "memory");
        } else {
            asm volatile("cp.async.wait_group 0;" ::: "memory");
        }
        __syncthreads();

        const uint32_t* uV = reinterpret_cast<const uint32_t*>(sVd + (t & 1) * VFLO);
        const uint32_t kSharedT = kShared0 + (uint32_t)((t & 1) * KFLO * 4);
        const int kt = t * BN;
        const bool dom = CAUSAL && (kt + BN > q0);

        uint32_t pa0 = 0, pa1 = 0, pa2 = 0, pa3 = 0;  // P A-frag of slice s-1

        #pragma unroll
        for (int s = 0; s < 8; s++) {
            // ---- K B-frags for slice s via ldmatrix.x4 ----
            uint32_t kb[16];
            const uint32_t sa = kSharedT + (uint32_t)(s * 8 * KSK * 4);
            ldsm4(kb[0],  kb[1],  kb[2],  kb[3],  sa);
            ldsm4(kb[4],  kb[5],  kb[6],  kb[7],  sa + 64);
            ldsm4(kb[8],  kb[9],  kb[10], kb[11], sa + 128);
            ldsm4(kb[12], kb[13], kb[14], kb[15], sa + 192);

            // ---- S slice (s): two independent accumulator chains ----
            float cA0 = 0.f, cA1 = 0.f, cA2 = 0.f, cA3 = 0.f;  // kk 0-3
            float cB0 = 0.f, cB1 = 0.f, cB2 = 0.f, cB3 = 0.f;  // kk 4-7
            #pragma unroll
            for (int kk = 0; kk < 4; kk++) {
                mma_tf32(cA0, cA1, cA2, cA3,
                         qf[kk][0], qf[kk][1], qf[kk][2], qf[kk][3],
                         kb[kk * 2], kb[kk * 2 + 1]);
                mma_tf32(cB0, cB1, cB2, cB3,
                         qf[kk + 4][0], qf[kk + 4][1], qf[kk + 4][2], qf[kk + 4][3],
                         kb[8 + kk * 2], kb[8 + kk * 2 + 1]);
            }

            // ---- PV for slice s-1 (independent of S(s): overlaps the
            //      S-MMA chain latency and the exp of slice s-1) ----
            if (s > 0) {
                const int sp = s - 1;
                #pragma unroll
                for (int dt = 0; dt < 8; dt++) {
                    uint32_t b0 = uV[(sp * 8 + c) * KSV + dt * 8 + g];
                    uint32_t b1 = uV[(sp * 8 + c + 4) * KSV + dt * 8 + g];
                    mma_tf32(o[dt * 4 + 0], o[dt * 4 + 1],
                             o[dt * 4 + 2], o[dt * 4 + 3],
                             pa0, pa1, pa2, pa3, b0, b1);
                }
            }

            // ---- consume S(s): ex2 + causal mask ----
            float s0 = cA0 + cB0, s1 = cA1 + cB1;
            float s2 = cA2 + cB2, s3 = cA3 + cB3;
            float p0, p1, p2, p3;
            if (dom) {
                int k0 = kt + s * 8 + 2 * c;
                p0 = (k0     > r0q) ? 0.f : ex2f(s0);
                p1 = (k0 + 1 > r0q) ? 0.f : ex2f(s1);
                p2 = (k0     > r1q) ? 0.f : ex2f(s2);
                p3 = (k0 + 1 > r1q) ? 0.f : ex2f(s3);
            } else {
                p0 = ex2f(s0); p1 = ex2f(s1);
                p2 = ex2f(s2); p3 = ex2f(s3);
            }
            // RNA-round p to tf32 so rs and MMA see identical values.
            uint32_t u0 = f2tf(p0), u1 = f2tf(p1);
            uint32_t u2 = f2tf(p2), u3 = f2tf(p3);
            rs0 += __uint_as_float(u0) + __uint_as_float(u1);
            rs1 += __uint_as_float(u2) + __uint_as_float(u3);

            // ---- C-layout IS the A-frag under the V row permutation ----
            // A[g][c]=P[key 2c]=u0, A[g+8][c]=u2, A[g][c+4]=P[key 2c+1]=u1,
            // A[g+8][c+4]=u3  (V row n stored at sigma(n)=(n&1)*4+(n>>1)).
            pa0 = u0;
            pa1 = u2;
            pa2 = u1;
            pa3 = u3;
        }

        // ---- drain: PV for slice 7 of this tile ----
        {
            #pragma unroll
            for (int dt = 0; dt < 8; dt++) {
                uint32_t b0 = uV[(7 * 8 + c) * KSV + dt * 8 + g];
                uint32_t b1 = uV[(7 * 8 + c + 4) * KSV + dt * 8 + g];
                mma_tf32(o[dt * 4 + 0], o[dt * 4 + 1],
                         o[dt * 4 + 2], o[dt * 4 + 3],
                         pa0, pa1, pa2, pa3, b0, b1);
            }
        }
        __syncthreads();
    }

    // Reduce row sums across the quad.
    rs0 += __shfl_xor_sync(0xffffffffu, rs0, 1);
    rs0 += __shfl_xor_sync(0xffffffffu, rs0, 2);
    rs1 += __shfl_xor_sync(0xffffffffu, rs1, 1);
    rs1 += __shfl_xor_sync(0xffffffffu, rs1, 2);
    float inv0 = lw / rs0;
    float inv1 = lw / rs1;
    #pragma unroll
    for (int dt = 0; dt < 8; dt++) {
        tot[dt * 4 + 0] = fmaf(o[dt * 4 + 0], inv0, tot[dt * 4 + 0]);
        tot[dt * 4 + 1] = fmaf(o[dt * 4 + 1], inv0, tot[dt * 4 + 1]);
        tot[dt * 4 + 2] = fmaf(o[dt * 4 + 2], inv1, tot[dt * 4 + 2]);
        tot[dt * 4 + 3] = fmaf(o[dt * 4 + 3], inv1, tot[dt * 4 + 3]);
    }
}

__global__ __launch_bounds__(128, 3)
void xlvl_attn_mma_kernel(
    const float* __restrict__ Q,
    const float* __restrict__ K0, const float* __restrict__ V0,
    const float* __restrict__ K1, const float* __restrict__ V1,
    const float* __restrict__ K2, const float* __restrict__ V2,
    const float* __restrict__ logits,
    float* __restrict__ out,
    int T, int T1, int T2)
{
    extern __shared__ __align__(16) float dynsmem[];
    float* sKd = dynsmem;                 // 2 x 64 x 68
    float* sVd = dynsmem + 2 * KFLO;      // 2 x 64 x 72

    const int qb  = (int)(gridDim.x - 1 - blockIdx.x);  // heavy blocks first
    const int h   = blockIdx.y;
    const int b   = blockIdx.z;
    const int tid = threadIdx.x;
    const int w   = tid >> 5;
    const int ln  = tid & 31;
    const int g   = ln >> 2;
    const int c   = ln & 3;
    const int q0  = qb * BM;
    const int r0q = q0 + w * 16 + g;

    // Per-lane ldmatrix byte offset inside a K tile:
    // matrix m = ln>>3 on rows (ln&7), col offset (m>>1)*8 + (m&1)*4 floats.
    const int lm_m = ln >> 3;
    const int lm_r = ln & 7;
    const uint32_t kOff =
        (uint32_t)((lm_r * KSK + (lm_m >> 1) * 8 + (lm_m & 1) * 4) * 4);

    float l0 = logits[0], l1 = logits[1], l2 = logits[2];
    float mx = fmaxf(l0, fmaxf(l1, l2));
    float e0 = __expf(l0 - mx), e1 = __expf(l1 - mx), e2 = __expf(l2 - mx);
    float winv = 1.0f / (e0 + e1 + e2);
    float w0 = e0 * winv, w1 = e1 * winv, w2 = e2 * winv;

    // Q A-fragments (RNA tf32), SCALE*log2e folded; shared by all levels.
    uint32_t qf[8][4];
    {
        const float* qp  = Q + ((size_t)(b * NHEAD + h) * T + r0q) * DH;
        const float* qp8 = qp + 8 * DH;
        #pragma unroll
        for (int kk = 0; kk < 8; kk++) {
            qf[kk][0] = f2tf(qp [kk * 8 + c]     * SCALE_L2E);
            qf[kk][1] = f2tf(qp8[kk * 8 + c]     * SCALE_L2E);
            qf[kk][2] = f2tf(qp [kk * 8 + c + 4] * SCALE_L2E);
            qf[kk][3] = f2tf(qp8[kk * 8 + c + 4] * SCALE_L2E);
        }
    }

    float tot[32];
    #pragma unroll
    for (int i = 0; i < 32; i++) tot[i] = 0.f;

    attend_level<true>(K0 + (size_t)b * T  * CDIM + h * DH,
                       V0 + (size_t)b * T  * CDIM + h * DH,
                       q0 + BM, q0, ln, g, c, tid, r0q, qf, tot, w0,
                       sKd, sVd, kOff);
    attend_level<false>(K1 + (size_t)b * T1 * CDIM + h * DH,
                        V1 + (size_t)b * T1 * CDIM + h * DH,
                        T1, q0, ln, g, c, tid, r0q, qf, tot, w1,
                        sKd, sVd, kOff);
    attend_level<false>(K2 + (size_t)b * T2 * CDIM + h * DH,
                        V2 + (size_t)b * T2 * CDIM + h * DH,
                        T2, q0, ln, g, c, tid, r0q, qf, tot, w2,
                        sKd, sVd, kOff);

    float* op0 = out + ((size_t)b * T + r0q) * CDIM + h * DH;
    float* op1 = op0 + 8 * CDIM;
    #pragma unroll
    for (int dt = 0; dt < 8; dt++) {
        *reinterpret_cast<float2*>(op0 + dt * 8 + 2 * c) =
            make_float2(tot[dt * 4 + 0], tot[dt * 4 + 1]);
        *reinterpret_cast<float2*>(op1 + dt * 8 + 2 * c) =
            make_float2(tot[dt * 4 + 2], tot[dt * 4 + 3]);
    }
}

extern "C" void kernel_launch(void* const* d_in, const int* in_sizes, int n_in,
                              void* d_out, int out_size)
{
    const float* Q      = (const float*)d_in[0];
    const float* K0     = (const float*)d_in[1];
    const float* V0     = (const float*)d_in[2];
    const float* K1     = (const float*)d_in[3];
    const float* V1     = (const float*)d_in[4];
    const float* K2     = (const float*)d_in[5];
    const float* V2     = (const float*)d_in[6];
    const float* logits = (const float*)d_in[7];
    float* out          = (float*)d_out;

    const int B  = 2;
    const int T  = in_sizes[1] / (B * CDIM);
    const int T1 = in_sizes[3] / (B * CDIM);
    const int T2 = in_sizes[5] / (B * CDIM);

    const int smem = (2 * KFLO + 2 * VFLO) * (int)sizeof(float);  // 71,680 B
    static bool configured = false;
    if (!configured) {
        cudaFuncSetAttribute(xlvl_attn_mma_kernel,
                             cudaFuncAttributeMaxDynamicSharedMemorySize, smem);
        configured = true;
    }

    dim3 grid(T / BM, NHEAD, B);
    xlvl_attn_mma_kernel<<<grid, 128, smem>>>(Q, K0, V0, K1, V1, K2, V2, logits,
                                              out, T, T1, T2);
}